// round 5
// baseline (speedup 1.0000x reference)
#include <cuda_runtime.h>

#define N_USER   50000
#define N_ITEM   100000
#define N_NODES  150000
#define EMB      64
#define N_LAYERS 3
#define NNZ      2400000
#define BATCH    4096
#define ROWELEMS (N_NODES * EMB)     // 9,600,000 floats = 38.4 MB per buffer
#define SCAN_BLOCKS 586              // ceil(N_NODES / 256)

// Persistent scratch (static __device__ arrays: no runtime allocation).
__device__ float g_ego[N_LAYERS + 1][ROWELEMS];
__device__ float g_norm[N_LAYERS][ROWELEMS];

// CSR build scratch
__device__ int  g_cnt[N_NODES];
__device__ int  g_off[N_NODES + 1];
__device__ int  g_cur[N_NODES];
__device__ int  g_bsum[SCAN_BLOCKS];
__device__ int  g_bpre[SCAN_BLOCKS];
__device__ int2 g_edge[NNZ];         // (col, float-bits of val), grouped by row

// packed f32x2 FMA: acc = a*b + acc
#define FMA2(acc, a, b) \
    asm("fma.rn.f32x2 %0, %1, %2, %3;" : "=l"(acc) : "l"(a), "l"(b), "l"(acc))

__device__ __forceinline__ float f2lo(unsigned long long v) {
    return __uint_as_float((unsigned)(v & 0xffffffffull));
}
__device__ __forceinline__ float f2hi(unsigned long long v) {
    return __uint_as_float((unsigned)(v >> 32));
}

// ---------------------------------------------------------------------------
// init: ego0 = concat(user_emb, item_emb)
// ---------------------------------------------------------------------------
__global__ void init_kernel(const float4* __restrict__ ue, const float4* __restrict__ ie) {
    int i = blockIdx.x * blockDim.x + threadIdx.x;
    const int NU4 = N_USER * EMB / 4;
    const int NT4 = ROWELEMS / 4;
    if (i >= NT4) return;
    float4 v = (i < NU4) ? ue[i] : ie[i - NU4];
    reinterpret_cast<float4*>(g_ego[0])[i] = v;
}

// ---------------------------------------------------------------------------
// CSR build: zero counts -> histogram -> 2-level exclusive scan -> scatter
// ---------------------------------------------------------------------------
__global__ void zero_cnt_kernel() {
    int i = blockIdx.x * blockDim.x + threadIdx.x;
    if (i < N_NODES) g_cnt[i] = 0;
}

__global__ void hist_kernel(const int* __restrict__ arow) {
    int e = blockIdx.x * blockDim.x + threadIdx.x;
    if (e >= NNZ) return;
    atomicAdd(&g_cnt[arow[e]], 1);
}

__global__ void scan1_kernel() {            // per-block sums of 256 counts
    __shared__ int s[256];
    int t = threadIdx.x;
    int i = blockIdx.x * 256 + t;
    s[t] = (i < N_NODES) ? g_cnt[i] : 0;
    __syncthreads();
    for (int d = 128; d > 0; d >>= 1) {
        if (t < d) s[t] += s[t + d];
        __syncthreads();
    }
    if (t == 0) g_bsum[blockIdx.x] = s[0];
}

__global__ void scan2_kernel() {            // single-block exclusive scan of block sums
    __shared__ int s[1024];
    int t = threadIdx.x;
    int v = (t < SCAN_BLOCKS) ? g_bsum[t] : 0;
    s[t] = v;
    __syncthreads();
    for (int d = 1; d < 1024; d <<= 1) {
        int add = (t >= d) ? s[t - d] : 0;
        __syncthreads();
        s[t] += add;
        __syncthreads();
    }
    if (t < SCAN_BLOCKS) g_bpre[t] = s[t] - v;   // exclusive
    if (t == 0) g_off[N_NODES] = NNZ;
}

__global__ void scan3_kernel() {            // final offsets
    __shared__ int s[256];
    int t = threadIdx.x;
    int i = blockIdx.x * 256 + t;
    int v = (i < N_NODES) ? g_cnt[i] : 0;
    s[t] = v;
    __syncthreads();
    for (int d = 1; d < 256; d <<= 1) {
        int add = (t >= d) ? s[t - d] : 0;
        __syncthreads();
        s[t] += add;
        __syncthreads();
    }
    if (i < N_NODES) {
        int off = g_bpre[blockIdx.x] + s[t] - v;
        g_off[i] = off;
        g_cur[i] = off;
    }
}

__global__ void scatter_kernel(const int* __restrict__ arow,
                               const int* __restrict__ acol,
                               const float* __restrict__ aval) {
    int e = blockIdx.x * blockDim.x + threadIdx.x;
    if (e >= NNZ) return;
    int r = arow[e];
    int pos = atomicAdd(&g_cur[r], 1);
    g_edge[pos] = make_int2(acol[e], __float_as_int(aval[e]));
}

// ---------------------------------------------------------------------------
// FUSED layer: SpMM (warp-per-row into smem) + dense GEMM + lrelu + norm.
//   side = segsum(val * ego[col]);  h = side; p = ego * side   (in smem)
//   out  = lrelu(h@Wg + p@Wb + bg + bb);  norm_out = out/||out||
// 64x64 block tile, 256 threads, 4x4 thread tile, f32x2 accumulators.
// sH/sP padded to stride 17 (16B units) -> conflict-free.
// ---------------------------------------------------------------------------
#define HP_STRIDE 17
__global__ void __launch_bounds__(256, 2) fused_layer_kernel(
        const float4* __restrict__ Wgc, const float* __restrict__ bgc,
        const float4* __restrict__ Wbi, const float* __restrict__ bbi,
        int k) {
    extern __shared__ char smem[];
    ulonglong2* sH  = reinterpret_cast<ulonglong2*>(smem);                 // 64*17*16 = 17408
    ulonglong2* sP  = reinterpret_cast<ulonglong2*>(smem + 17408);         // 17408
    ulonglong2* sWg = reinterpret_cast<ulonglong2*>(smem + 34816);         // 16384
    ulonglong2* sWb = reinterpret_cast<ulonglong2*>(smem + 51200);         // 16384
    float*      sB  = reinterpret_cast<float*>(smem + 67584);              // 256

    const int tid  = threadIdx.x;
    const int wid  = tid >> 5;
    const int lane = tid & 31;
    const int row0 = blockIdx.x * 64;

    // ---- stage W transposed + XOR swizzle: (kk,c) -> sW[c*16 + ((kk>>2)^(c&7))].f[kk&3]
    for (int i = tid; i < 64 * 16; i += 256) {
        int kk = i >> 4;
        int c4 = i & 15;
        float4 wg = Wgc[i];
        float4 wb = Wbi[i];
        const float* wgf = reinterpret_cast<const float*>(&wg);
        const float* wbf = reinterpret_cast<const float*>(&wb);
        int k4 = kk >> 2, ksub = kk & 3;
        #pragma unroll
        for (int j = 0; j < 4; j++) {
            int c = c4 * 4 + j;
            int idx = c * 16 + (k4 ^ (c & 7));
            reinterpret_cast<float*>(&sWg[idx])[ksub] = wgf[j];
            reinterpret_cast<float*>(&sWb[idx])[ksub] = wbf[j];
        }
    }
    if (tid < 64) sB[tid] = bgc[tid] + bbi[tid];

    // ---- in-block SpMM: warp w computes rows row0 + w*8 .. w*8+7
    // lane owns cols {2*lane, 2*lane+1}; result written straight into sH/sP.
    {
        float* sHf = reinterpret_cast<float*>(sH);
        float* sPf = reinterpret_cast<float*>(sP);
        const float* __restrict__ ego = g_ego[k];
        #pragma unroll 1
        for (int i = 0; i < 8; i++) {
            int r = wid * 8 + i;
            int row = row0 + r;
            float2 acc = make_float2(0.f, 0.f);
            float2 e2  = make_float2(0.f, 0.f);
            if (row < N_NODES) {
                int beg = __ldg(&g_off[row]);
                int end = __ldg(&g_off[row + 1]);
                for (int e = beg; e < end; e++) {
                    int2 cv = g_edge[e];                       // broadcast
                    float v = __int_as_float(cv.y);
                    float2 x = reinterpret_cast<const float2*>(
                                   ego + (size_t)cv.x * EMB)[lane];
                    acc.x += v * x.x;
                    acc.y += v * x.y;
                }
                e2 = reinterpret_cast<const float2*>(ego + (size_t)row * EMB)[lane];
            }
            int off = r * (HP_STRIDE * 4) + 2 * lane;          // float offset
            *reinterpret_cast<float2*>(sHf + off) = acc;
            *reinterpret_cast<float2*>(sPf + off) =
                make_float2(acc.x * e2.x, acc.y * e2.y);
        }
    }
    __syncthreads();

    // ---- dense GEMM mainloop
    const int cg = tid & 15;
    const int rg = tid >> 4;

    unsigned long long acc[4][4];
    #pragma unroll
    for (int a = 0; a < 4; a++)
        #pragma unroll
        for (int b = 0; b < 4; b++) acc[a][b] = 0ull;

    int ccol[4], widx[4];
    #pragma unroll
    for (int cidx = 0; cidx < 4; cidx++) {
        ccol[cidx] = cidx * 16 + cg;
        widx[cidx] = ccol[cidx] * 16;
    }

    #pragma unroll 4
    for (int k4 = 0; k4 < 16; k4++) {
        ulonglong2 h2[4], p2[4];
        #pragma unroll
        for (int ridx = 0; ridx < 4; ridx++) {
            int r = rg * 4 + ridx;
            h2[ridx] = sH[r * HP_STRIDE + k4];
            p2[ridx] = sP[r * HP_STRIDE + k4];
        }
        ulonglong2 wg2[4], wb2[4];
        #pragma unroll
        for (int cidx = 0; cidx < 4; cidx++) {
            int idx = widx[cidx] + (k4 ^ (ccol[cidx] & 7));
            wg2[cidx] = sWg[idx];
            wb2[cidx] = sWb[idx];
        }
        #pragma unroll
        for (int ridx = 0; ridx < 4; ridx++) {
            #pragma unroll
            for (int cidx = 0; cidx < 4; cidx++) {
                FMA2(acc[ridx][cidx], h2[ridx].x, wg2[cidx].x);
                FMA2(acc[ridx][cidx], h2[ridx].y, wg2[cidx].y);
                FMA2(acc[ridx][cidx], p2[ridx].x, wb2[cidx].x);
                FMA2(acc[ridx][cidx], p2[ridx].y, wb2[cidx].y);
            }
        }
    }

    // ---- epilogue: combine lanes, bias, leaky_relu, row-norm via half-warp shuffle
    float out[4][4];
    float ssr[4];
    #pragma unroll
    for (int ridx = 0; ridx < 4; ridx++) {
        ssr[ridx] = 0.f;
        #pragma unroll
        for (int cidx = 0; cidx < 4; cidx++) {
            float v = f2lo(acc[ridx][cidx]) + f2hi(acc[ridx][cidx]) + sB[ccol[cidx]];
            v = (v > 0.f) ? v : 0.2f * v;
            out[ridx][cidx] = v;
            ssr[ridx] += v * v;
        }
    }
    #pragma unroll
    for (int ridx = 0; ridx < 4; ridx++) {
        float s = ssr[ridx];
        #pragma unroll
        for (int m = 1; m < 16; m <<= 1)
            s += __shfl_xor_sync(0xffffffffu, s, m, 16);
        ssr[ridx] = 1.0f / fmaxf(sqrtf(s), 1e-12f);
    }

    float* __restrict__ egonew  = g_ego[k + 1];
    float* __restrict__ normout = g_norm[k];
    #pragma unroll
    for (int ridx = 0; ridx < 4; ridx++) {
        int row = row0 + rg * 4 + ridx;
        if (row < N_NODES) {
            #pragma unroll
            for (int cidx = 0; cidx < 4; cidx++) {
                float v = out[ridx][cidx];
                egonew [(size_t)row * EMB + ccol[cidx]] = v;
                normout[(size_t)row * EMB + ccol[cidx]] = v * ssr[ridx];
            }
        }
    }
}

// ---------------------------------------------------------------------------
// Final gather: out rows = [ego_init | norm0 | norm1 | norm2] at selected nodes.
// ---------------------------------------------------------------------------
__global__ void gather_kernel(const int* __restrict__ users,
                              const int* __restrict__ pos,
                              const int* __restrict__ neg,
                              float* __restrict__ out) {
    int t = blockIdx.x * blockDim.x + threadIdx.x;
    if (t >= 3 * BATCH * 64) return;
    int q = t & 63;
    int r = t >> 6;
    int s = r / BATCH;
    int b = r - s * BATCH;
    int node = (s == 0) ? users[b] : (N_USER + ((s == 1) ? pos[b] : neg[b]));
    int blk = q >> 4;
    int qq  = q & 15;
    const float* src = (blk == 0) ? g_ego[0] : g_norm[blk - 1];
    float4 v = *reinterpret_cast<const float4*>(src + (size_t)node * EMB + qq * 4);
    reinterpret_cast<float4*>(out)[(size_t)r * 64 + q] = v;
}

// ---------------------------------------------------------------------------
extern "C" void kernel_launch(void* const* d_in, const int* in_sizes, int n_in,
                              void* d_out, int out_size) {
    const int*   users    = (const int*)  d_in[0];
    const int*   pos      = (const int*)  d_in[1];
    const int*   neg      = (const int*)  d_in[2];
    const int*   arow     = (const int*)  d_in[3];
    const int*   acol     = (const int*)  d_in[4];
    const float* aval     = (const float*)d_in[5];
    const float* user_emb = (const float*)d_in[6];
    const float* item_emb = (const float*)d_in[7];
    const float* W_gc     = (const float*)d_in[8];
    const float* b_gc     = (const float*)d_in[9];
    const float* W_bi     = (const float*)d_in[10];
    const float* b_bi     = (const float*)d_in[11];
    float* out = (float*)d_out;

    const int DSMEM = 67584 + 256;
    static int attr_done = 0;
    if (!attr_done) {
        cudaFuncSetAttribute(fused_layer_kernel, cudaFuncAttributeMaxDynamicSharedMemorySize, DSMEM);
        attr_done = 1;
    }

    const int VEC_BLOCKS    = (ROWELEMS / 4 + 255) / 256;       // 9375
    const int EDGE_BLOCKS   = (NNZ + 255) / 256;                // 9375
    const int NODE_BLOCKS   = (N_NODES + 255) / 256;            // 586
    const int FUSED_BLOCKS  = (N_NODES + 63) / 64;              // 2344
    const int GATHER_BLOCKS = (3 * BATCH * 64 + 255) / 256;     // 3072

    init_kernel<<<VEC_BLOCKS, 256>>>((const float4*)user_emb, (const float4*)item_emb);

    // CSR build (once; reused by all 3 layers)
    zero_cnt_kernel<<<NODE_BLOCKS, 256>>>();
    hist_kernel<<<EDGE_BLOCKS, 256>>>(arow);
    scan1_kernel<<<SCAN_BLOCKS, 256>>>();
    scan2_kernel<<<1, 1024>>>();
    scan3_kernel<<<SCAN_BLOCKS, 256>>>();
    scatter_kernel<<<EDGE_BLOCKS, 256>>>(arow, acol, aval);

    for (int k = 0; k < N_LAYERS; k++) {
        fused_layer_kernel<<<FUSED_BLOCKS, 256, DSMEM>>>(
            (const float4*)(W_gc + k * EMB * EMB), b_gc + k * EMB,
            (const float4*)(W_bi + k * EMB * EMB), b_bi + k * EMB, k);
    }

    gather_kernel<<<GATHER_BLOCKS, 256>>>(users, pos, neg, out);
}

// round 9
// speedup vs baseline: 1.2743x; 1.2743x over previous
#include <cuda_runtime.h>
#include <cuda_fp16.h>

#define N_USER   50000
#define N_ITEM   100000
#define N_NODES  150000
#define EMB      64
#define N_LAYERS 3
#define NNZ      2400000
#define BATCH    4096
#define ROWELEMS (N_NODES * EMB)     // 9,600,000 floats = 38.4 MB per buffer
#define SCAN_BLOCKS 586              // ceil(N_NODES / 256)

// Persistent scratch (static __device__ arrays: no runtime allocation).
__device__ float  g_ego[N_LAYERS + 1][ROWELEMS];
__device__ float  g_norm[N_LAYERS][ROWELEMS];
__device__ float  g_side[ROWELEMS];
__device__ __half g_egoh[ROWELEMS];  // fp16 mirror of the CURRENT layer's ego (spmm gather operand)

// CSR build scratch
__device__ int  g_cnt[N_NODES];
__device__ int  g_off[N_NODES + 1];
__device__ int  g_cur[N_NODES];
__device__ int  g_bsum[SCAN_BLOCKS];
__device__ int  g_bpre[SCAN_BLOCKS];
__device__ int2 g_edge[NNZ];         // (col, float-bits of val), grouped by row

// packed f32x2 FMA: acc = a*b + acc
#define FMA2(acc, a, b) \
    asm("fma.rn.f32x2 %0, %1, %2, %3;" : "=l"(acc) : "l"(a), "l"(b), "l"(acc))

__device__ __forceinline__ float f2lo(unsigned long long v) {
    return __uint_as_float((unsigned)(v & 0xffffffffull));
}
__device__ __forceinline__ float f2hi(unsigned long long v) {
    return __uint_as_float((unsigned)(v >> 32));
}

// ---------------------------------------------------------------------------
// init: ego0 = concat(user_emb, item_emb), plus fp16 mirror
// ---------------------------------------------------------------------------
__global__ void init_kernel(const float4* __restrict__ ue, const float4* __restrict__ ie) {
    int i = blockIdx.x * blockDim.x + threadIdx.x;
    const int NU4 = N_USER * EMB / 4;
    const int NT4 = ROWELEMS / 4;
    if (i >= NT4) return;
    float4 v = (i < NU4) ? ue[i] : ie[i - NU4];
    reinterpret_cast<float4*>(g_ego[0])[i] = v;
    __half2* h2 = reinterpret_cast<__half2*>(g_egoh) + i * 2;
    h2[0] = __floats2half2_rn(v.x, v.y);
    h2[1] = __floats2half2_rn(v.z, v.w);
}

// ---------------------------------------------------------------------------
// CSR build: zero counts -> histogram -> 2-level exclusive scan -> scatter
// ---------------------------------------------------------------------------
__global__ void zero_cnt_kernel() {
    int i = blockIdx.x * blockDim.x + threadIdx.x;
    if (i < N_NODES) g_cnt[i] = 0;
}

__global__ void hist_kernel(const int* __restrict__ arow) {
    int e = blockIdx.x * blockDim.x + threadIdx.x;
    if (e >= NNZ) return;
    atomicAdd(&g_cnt[arow[e]], 1);
}

__global__ void scan1_kernel() {            // per-block sums of 256 counts
    __shared__ int s[256];
    int t = threadIdx.x;
    int i = blockIdx.x * 256 + t;
    s[t] = (i < N_NODES) ? g_cnt[i] : 0;
    __syncthreads();
    for (int d = 128; d > 0; d >>= 1) {
        if (t < d) s[t] += s[t + d];
        __syncthreads();
    }
    if (t == 0) g_bsum[blockIdx.x] = s[0];
}

__global__ void scan2_kernel() {            // single-block exclusive scan of block sums
    __shared__ int s[1024];
    int t = threadIdx.x;
    int v = (t < SCAN_BLOCKS) ? g_bsum[t] : 0;
    s[t] = v;
    __syncthreads();
    for (int d = 1; d < 1024; d <<= 1) {
        int add = (t >= d) ? s[t - d] : 0;
        __syncthreads();
        s[t] += add;
        __syncthreads();
    }
    if (t < SCAN_BLOCKS) g_bpre[t] = s[t] - v;   // exclusive
    if (t == 0) g_off[N_NODES] = NNZ;
}

__global__ void scan3_kernel() {            // final offsets
    __shared__ int s[256];
    int t = threadIdx.x;
    int i = blockIdx.x * 256 + t;
    int v = (i < N_NODES) ? g_cnt[i] : 0;
    s[t] = v;
    __syncthreads();
    for (int d = 1; d < 256; d <<= 1) {
        int add = (t >= d) ? s[t - d] : 0;
        __syncthreads();
        s[t] += add;
        __syncthreads();
    }
    if (i < N_NODES) {
        int off = g_bpre[blockIdx.x] + s[t] - v;
        g_off[i] = off;
        g_cur[i] = off;
    }
}

__global__ void scatter_kernel(const int* __restrict__ arow,
                               const int* __restrict__ acol,
                               const float* __restrict__ aval) {
    int e = blockIdx.x * blockDim.x + threadIdx.x;
    if (e >= NNZ) return;
    int r = arow[e];
    int pos = atomicAdd(&g_cur[r], 1);
    g_edge[pos] = make_int2(acol[e], __float_as_int(aval[e]));
}

// ---------------------------------------------------------------------------
// SpMM over CSR: warp per row, fp16 gather operand (half the L2 bytes),
// edge loop unrolled x4 for MLP. Lane owns cols {2l, 2l+1}; fp32 accumulate;
// one coalesced 256B fp32 store per row.
// ---------------------------------------------------------------------------
__global__ void spmm_sorted_kernel() {
    int gtid = blockIdx.x * blockDim.x + threadIdx.x;
    int row  = gtid >> 5;
    if (row >= N_NODES) return;
    int lane = threadIdx.x & 31;

    int beg = g_off[row];
    int end = g_off[row + 1];
    const __half2* __restrict__ egoh = reinterpret_cast<const __half2*>(g_egoh);

    float2 acc = make_float2(0.f, 0.f);
    int e = beg;
    for (; e + 4 <= end; e += 4) {
        int2 c0 = g_edge[e + 0];
        int2 c1 = g_edge[e + 1];
        int2 c2 = g_edge[e + 2];
        int2 c3 = g_edge[e + 3];
        __half2 x0 = egoh[c0.x * 32 + lane];
        __half2 x1 = egoh[c1.x * 32 + lane];
        __half2 x2 = egoh[c2.x * 32 + lane];
        __half2 x3 = egoh[c3.x * 32 + lane];
        float2 f0 = __half22float2(x0);
        float2 f1 = __half22float2(x1);
        float2 f2 = __half22float2(x2);
        float2 f3 = __half22float2(x3);
        float v0 = __int_as_float(c0.y);
        float v1 = __int_as_float(c1.y);
        float v2 = __int_as_float(c2.y);
        float v3 = __int_as_float(c3.y);
        acc.x += v0 * f0.x; acc.y += v0 * f0.y;
        acc.x += v1 * f1.x; acc.y += v1 * f1.y;
        acc.x += v2 * f2.x; acc.y += v2 * f2.y;
        acc.x += v3 * f3.x; acc.y += v3 * f3.y;
    }
    for (; e < end; e++) {
        int2 cv = g_edge[e];
        float v = __int_as_float(cv.y);
        float2 f = __half22float2(egoh[cv.x * 32 + lane]);
        acc.x += v * f.x;
        acc.y += v * f.y;
    }
    reinterpret_cast<float2*>(g_side + (size_t)row * EMB)[lane] = acc;
}

// ---------------------------------------------------------------------------
// Dense: out = lrelu(h@Wg + (ego*h)@Wb + b), then row-normalize.
// 64x64 block tile, 256 threads, 4x4 thread tile, f32x2 accumulators.
// sH/sP padded to stride 17 (16B units) -> conflict-free.
// Epilogue also refreshes the fp16 ego mirror for the next layer's spmm.
// ---------------------------------------------------------------------------
#define HP_STRIDE 17
__global__ void __launch_bounds__(256, 2) dense_kernel(
        const float4* __restrict__ Wgc, const float* __restrict__ bgc,
        const float4* __restrict__ Wbi, const float* __restrict__ bbi,
        int k) {
    extern __shared__ char smem[];
    ulonglong2* sH  = reinterpret_cast<ulonglong2*>(smem);                 // 64*17*16 = 17408
    ulonglong2* sP  = reinterpret_cast<ulonglong2*>(smem + 17408);         // 17408
    ulonglong2* sWg = reinterpret_cast<ulonglong2*>(smem + 34816);         // 16384
    ulonglong2* sWb = reinterpret_cast<ulonglong2*>(smem + 51200);         // 16384
    float*      sB  = reinterpret_cast<float*>(smem + 67584);              // 256

    const int tid = threadIdx.x;
    const int row0 = blockIdx.x * 64;

    const float4* side4 = reinterpret_cast<const float4*>(g_side);
    const float4* ego4  = reinterpret_cast<const float4*>(g_ego[k]);

    // stage h = side, p = ego*side
    for (int i = tid; i < 64 * 16; i += 256) {
        int r = i >> 4, c = i & 15;
        int rr = row0 + r;
        if (rr >= N_NODES) rr = N_NODES - 1;
        int gidx = rr * 16 + c;
        float4 s = side4[gidx];
        float4 e = ego4[gidx];
        *reinterpret_cast<float4*>(&sH[r * HP_STRIDE + c]) = s;
        *reinterpret_cast<float4*>(&sP[r * HP_STRIDE + c]) =
            make_float4(s.x * e.x, s.y * e.y, s.z * e.z, s.w * e.w);
    }
    // stage W transposed + XOR swizzle: (kk, c) -> sW[c*16 + ((kk>>2) ^ (c&7))].f[kk&3]
    for (int i = tid; i < 64 * 16; i += 256) {
        int kk = i >> 4;
        int c4 = i & 15;
        float4 wg = Wgc[i];
        float4 wb = Wbi[i];
        const float* wgf = reinterpret_cast<const float*>(&wg);
        const float* wbf = reinterpret_cast<const float*>(&wb);
        int k4 = kk >> 2, ksub = kk & 3;
        #pragma unroll
        for (int j = 0; j < 4; j++) {
            int c = c4 * 4 + j;
            int idx = c * 16 + (k4 ^ (c & 7));
            reinterpret_cast<float*>(&sWg[idx])[ksub] = wgf[j];
            reinterpret_cast<float*>(&sWb[idx])[ksub] = wbf[j];
        }
    }
    if (tid < 64) sB[tid] = bgc[tid] + bbi[tid];
    __syncthreads();

    const int cg = tid & 15;
    const int rg = tid >> 4;

    unsigned long long acc[4][4];
    #pragma unroll
    for (int a = 0; a < 4; a++)
        #pragma unroll
        for (int b = 0; b < 4; b++) acc[a][b] = 0ull;

    int ccol[4], widx[4];
    #pragma unroll
    for (int cidx = 0; cidx < 4; cidx++) {
        ccol[cidx] = cidx * 16 + cg;
        widx[cidx] = ccol[cidx] * 16;
    }

    #pragma unroll 4
    for (int k4 = 0; k4 < 16; k4++) {
        ulonglong2 h2[4], p2[4];
        #pragma unroll
        for (int ridx = 0; ridx < 4; ridx++) {
            int r = rg * 4 + ridx;
            h2[ridx] = sH[r * HP_STRIDE + k4];
            p2[ridx] = sP[r * HP_STRIDE + k4];
        }
        ulonglong2 wg2[4], wb2[4];
        #pragma unroll
        for (int cidx = 0; cidx < 4; cidx++) {
            int idx = widx[cidx] + (k4 ^ (ccol[cidx] & 7));
            wg2[cidx] = sWg[idx];
            wb2[cidx] = sWb[idx];
        }
        #pragma unroll
        for (int ridx = 0; ridx < 4; ridx++) {
            #pragma unroll
            for (int cidx = 0; cidx < 4; cidx++) {
                FMA2(acc[ridx][cidx], h2[ridx].x, wg2[cidx].x);
                FMA2(acc[ridx][cidx], h2[ridx].y, wg2[cidx].y);
                FMA2(acc[ridx][cidx], p2[ridx].x, wb2[cidx].x);
                FMA2(acc[ridx][cidx], p2[ridx].y, wb2[cidx].y);
            }
        }
    }

    // epilogue: combine lanes, bias, leaky_relu, row-norm via half-warp shuffle
    float out[4][4];
    float ssr[4];
    #pragma unroll
    for (int ridx = 0; ridx < 4; ridx++) {
        ssr[ridx] = 0.f;
        #pragma unroll
        for (int cidx = 0; cidx < 4; cidx++) {
            float v = f2lo(acc[ridx][cidx]) + f2hi(acc[ridx][cidx]) + sB[ccol[cidx]];
            v = (v > 0.f) ? v : 0.2f * v;
            out[ridx][cidx] = v;
            ssr[ridx] += v * v;
        }
    }
    #pragma unroll
    for (int ridx = 0; ridx < 4; ridx++) {
        float s = ssr[ridx];
        #pragma unroll
        for (int m = 1; m < 16; m <<= 1)
            s += __shfl_xor_sync(0xffffffffu, s, m, 16);
        ssr[ridx] = 1.0f / fmaxf(sqrtf(s), 1e-12f);
    }

    float*  __restrict__ egonew  = g_ego[k + 1];
    float*  __restrict__ normout = g_norm[k];
    __half* __restrict__ egoh    = g_egoh;
    #pragma unroll
    for (int ridx = 0; ridx < 4; ridx++) {
        int row = row0 + rg * 4 + ridx;
        if (row < N_NODES) {
            #pragma unroll
            for (int cidx = 0; cidx < 4; cidx++) {
                float v = out[ridx][cidx];
                egonew [(size_t)row * EMB + ccol[cidx]] = v;
                normout[(size_t)row * EMB + ccol[cidx]] = v * ssr[ridx];
                if (k + 1 < N_LAYERS)
                    egoh[(size_t)row * EMB + ccol[cidx]] = __float2half_rn(v);
            }
        }
    }
}

// ---------------------------------------------------------------------------
// Final gather: out rows = [ego_init | norm0 | norm1 | norm2] at selected nodes.
// ---------------------------------------------------------------------------
__global__ void gather_kernel(const int* __restrict__ users,
                              const int* __restrict__ pos,
                              const int* __restrict__ neg,
                              float* __restrict__ out) {
    int t = blockIdx.x * blockDim.x + threadIdx.x;
    if (t >= 3 * BATCH * 64) return;
    int q = t & 63;
    int r = t >> 6;
    int s = r / BATCH;
    int b = r - s * BATCH;
    int node = (s == 0) ? users[b] : (N_USER + ((s == 1) ? pos[b] : neg[b]));
    int blk = q >> 4;
    int qq  = q & 15;
    const float* src = (blk == 0) ? g_ego[0] : g_norm[blk - 1];
    float4 v = *reinterpret_cast<const float4*>(src + (size_t)node * EMB + qq * 4);
    reinterpret_cast<float4*>(out)[(size_t)r * 64 + q] = v;
}

// ---------------------------------------------------------------------------
extern "C" void kernel_launch(void* const* d_in, const int* in_sizes, int n_in,
                              void* d_out, int out_size) {
    const int*   users    = (const int*)  d_in[0];
    const int*   pos      = (const int*)  d_in[1];
    const int*   neg      = (const int*)  d_in[2];
    const int*   arow     = (const int*)  d_in[3];
    const int*   acol     = (const int*)  d_in[4];
    const float* aval     = (const float*)d_in[5];
    const float* user_emb = (const float*)d_in[6];
    const float* item_emb = (const float*)d_in[7];
    const float* W_gc     = (const float*)d_in[8];
    const float* b_gc     = (const float*)d_in[9];
    const float* W_bi     = (const float*)d_in[10];
    const float* b_bi     = (const float*)d_in[11];
    float* out = (float*)d_out;

    const int DSMEM = 67584 + 256;
    static int attr_done = 0;
    if (!attr_done) {
        cudaFuncSetAttribute(dense_kernel, cudaFuncAttributeMaxDynamicSharedMemorySize, DSMEM);
        attr_done = 1;
    }

    const int VEC_BLOCKS    = (ROWELEMS / 4 + 255) / 256;       // 9375
    const int EDGE_BLOCKS   = (NNZ + 255) / 256;                // 9375
    const int NODE_BLOCKS   = (N_NODES + 255) / 256;            // 586
    const int SPMM_BLOCKS   = (N_NODES * 32 + 255) / 256;       // 18750
    const int DENSE_BLOCKS  = (N_NODES + 63) / 64;              // 2344
    const int GATHER_BLOCKS = (3 * BATCH * 64 + 255) / 256;     // 3072

    init_kernel<<<VEC_BLOCKS, 256>>>((const float4*)user_emb, (const float4*)item_emb);

    // CSR build (once; reused by all 3 layers)
    zero_cnt_kernel<<<NODE_BLOCKS, 256>>>();
    hist_kernel<<<EDGE_BLOCKS, 256>>>(arow);
    scan1_kernel<<<SCAN_BLOCKS, 256>>>();
    scan2_kernel<<<1, 1024>>>();
    scan3_kernel<<<SCAN_BLOCKS, 256>>>();
    scatter_kernel<<<EDGE_BLOCKS, 256>>>(arow, acol, aval);

    for (int k = 0; k < N_LAYERS; k++) {
        spmm_sorted_kernel<<<SPMM_BLOCKS, 256>>>();
        dense_kernel<<<DENSE_BLOCKS, 256, DSMEM>>>(
            (const float4*)(W_gc + k * EMB * EMB), b_gc + k * EMB,
            (const float4*)(W_bi + k * EMB * EMB), b_bi + k * EMB, k);
    }

    gather_kernel<<<GATHER_BLOCKS, 256>>>(users, pos, neg, out);
}

// round 10
// speedup vs baseline: 1.2837x; 1.0073x over previous
#include <cuda_runtime.h>

#define N_USER   50000
#define N_ITEM   100000
#define N_NODES  150000
#define EMB      64
#define N_LAYERS 3
#define NNZ      2400000
#define BATCH    4096
#define ROWELEMS (N_NODES * EMB)     // 9,600,000 floats = 38.4 MB per buffer
#define CSR_BLOCKS 592               // 148 SMs * 4 blocks — fully co-resident

// Persistent scratch (static __device__ arrays: no runtime allocation).
__device__ float g_ego[N_LAYERS + 1][ROWELEMS];
__device__ float g_norm[N_LAYERS][ROWELEMS];
__device__ float g_side[ROWELEMS];

// CSR build scratch
__device__ int  g_cnt[N_NODES];
__device__ int  g_off[N_NODES + 1];
__device__ int  g_cur[N_NODES];
__device__ int  g_bsum[CSR_BLOCKS];
__device__ int2 g_edge[NNZ];         // (col, float-bits of val), grouped by row

// grid barrier state (persistent; cnt always returns to 0, gen monotonic)
__device__ unsigned g_bar_cnt = 0;
__device__ unsigned g_bar_gen = 0;

__device__ __forceinline__ void grid_barrier() {
    __syncthreads();
    if (threadIdx.x == 0) {
        unsigned my_gen = atomicAdd(&g_bar_gen, 0u);
        __threadfence();
        if (atomicAdd(&g_bar_cnt, 1u) == CSR_BLOCKS - 1) {
            g_bar_cnt = 0;
            __threadfence();
            atomicAdd(&g_bar_gen, 1u);
        } else {
            while (atomicAdd(&g_bar_gen, 0u) == my_gen) {}
        }
        __threadfence();
    }
    __syncthreads();
}

// packed f32x2 FMA: acc = a*b + acc
#define FMA2(acc, a, b) \
    asm("fma.rn.f32x2 %0, %1, %2, %3;" : "=l"(acc) : "l"(a), "l"(b), "l"(acc))

__device__ __forceinline__ float f2lo(unsigned long long v) {
    return __uint_as_float((unsigned)(v & 0xffffffffull));
}
__device__ __forceinline__ float f2hi(unsigned long long v) {
    return __uint_as_float((unsigned)(v >> 32));
}

// ---------------------------------------------------------------------------
// init: ego0 = concat(user_emb, item_emb)
// ---------------------------------------------------------------------------
__global__ void init_kernel(const float4* __restrict__ ue, const float4* __restrict__ ie) {
    int i = blockIdx.x * blockDim.x + threadIdx.x;
    const int NU4 = N_USER * EMB / 4;
    const int NT4 = ROWELEMS / 4;
    if (i >= NT4) return;
    float4 v = (i < NU4) ? ue[i] : ie[i - NU4];
    reinterpret_cast<float4*>(g_ego[0])[i] = v;
}

// ---------------------------------------------------------------------------
// Fused CSR prep: zero counts -> histogram -> 3-phase exclusive scan.
// Single grid-resident kernel with spin grid barriers (592 blocks, 4/SM).
// ---------------------------------------------------------------------------
__global__ void __launch_bounds__(256) csr_prep_kernel(const int* __restrict__ arow) {
    const int tid = threadIdx.x;
    const int gid = blockIdx.x * 256 + tid;
    const int nthreads = CSR_BLOCKS * 256;

    // phase 0: zero counts
    for (int i = gid; i < N_NODES; i += nthreads) g_cnt[i] = 0;
    grid_barrier();

    // phase 1: histogram
    for (int e = gid; e < NNZ; e += nthreads) atomicAdd(&g_cnt[arow[e]], 1);
    grid_barrier();

    // phase 2: per-block inclusive scan of 256 counts + block sum
    __shared__ int s[256];
    int myv = (gid < N_NODES) ? g_cnt[gid] : 0;
    s[tid] = myv;
    __syncthreads();
    #pragma unroll
    for (int d = 1; d < 256; d <<= 1) {
        int add = (tid >= d) ? s[tid - d] : 0;
        __syncthreads();
        s[tid] += add;
        __syncthreads();
    }
    int my_incl = s[tid];
    if (tid == 255) g_bsum[blockIdx.x] = s[255];
    grid_barrier();

    // phase 3: block 0 exclusive-scans the block sums (3 chunks of 256, carry)
    if (blockIdx.x == 0) {
        __shared__ int carry;
        if (tid == 0) carry = 0;
        __syncthreads();
        for (int base = 0; base < CSR_BLOCKS; base += 256) {
            int idx = base + tid;
            int v = (idx < CSR_BLOCKS) ? g_bsum[idx] : 0;
            s[tid] = v;
            __syncthreads();
            #pragma unroll
            for (int d = 1; d < 256; d <<= 1) {
                int add = (tid >= d) ? s[tid - d] : 0;
                __syncthreads();
                s[tid] += add;
                __syncthreads();
            }
            if (idx < CSR_BLOCKS) g_bsum[idx] = carry + s[tid] - v;  // exclusive
            __syncthreads();
            if (tid == 0) carry += s[255];
            __syncthreads();
        }
    }
    grid_barrier();

    // phase 4: final offsets
    if (gid < N_NODES) {
        int off = g_bsum[blockIdx.x] + my_incl - myv;
        g_off[gid] = off;
        g_cur[gid] = off;
    }
    if (gid == 0) g_off[N_NODES] = NNZ;
}

__global__ void scatter_kernel(const int* __restrict__ arow,
                               const int* __restrict__ acol,
                               const float* __restrict__ aval) {
    int e = blockIdx.x * blockDim.x + threadIdx.x;
    if (e >= NNZ) return;
    int r = arow[e];
    int pos = atomicAdd(&g_cur[r], 1);
    g_edge[pos] = make_int2(acol[e], __float_as_int(aval[e]));
}

// ---------------------------------------------------------------------------
// SpMM over CSR: warp per row, fp32 gather, edge loop unrolled x4 (4
// independent 8B gathers in flight). Lane owns cols {2l, 2l+1}; one
// coalesced 256B store per row.
// ---------------------------------------------------------------------------
__global__ void spmm_sorted_kernel(int ein) {
    int gtid = blockIdx.x * blockDim.x + threadIdx.x;
    int row  = gtid >> 5;
    if (row >= N_NODES) return;
    int lane = threadIdx.x & 31;

    int beg = g_off[row];
    int end = g_off[row + 1];
    const float2* __restrict__ ego2 =
        reinterpret_cast<const float2*>(g_ego[ein]);

    float2 acc = make_float2(0.f, 0.f);
    int e = beg;
    for (; e + 4 <= end; e += 4) {
        int2 c0 = g_edge[e + 0];
        int2 c1 = g_edge[e + 1];
        int2 c2 = g_edge[e + 2];
        int2 c3 = g_edge[e + 3];
        float2 x0 = ego2[c0.x * 32 + lane];
        float2 x1 = ego2[c1.x * 32 + lane];
        float2 x2 = ego2[c2.x * 32 + lane];
        float2 x3 = ego2[c3.x * 32 + lane];
        float v0 = __int_as_float(c0.y);
        float v1 = __int_as_float(c1.y);
        float v2 = __int_as_float(c2.y);
        float v3 = __int_as_float(c3.y);
        acc.x += v0 * x0.x; acc.y += v0 * x0.y;
        acc.x += v1 * x1.x; acc.y += v1 * x1.y;
        acc.x += v2 * x2.x; acc.y += v2 * x2.y;
        acc.x += v3 * x3.x; acc.y += v3 * x3.y;
    }
    for (; e < end; e++) {
        int2 cv = g_edge[e];
        float v = __int_as_float(cv.y);
        float2 x = ego2[cv.x * 32 + lane];
        acc.x += v * x.x;
        acc.y += v * x.y;
    }
    reinterpret_cast<float2*>(g_side + (size_t)row * EMB)[lane] = acc;
}

// ---------------------------------------------------------------------------
// Dense: out = lrelu(h@Wg + (ego*h)@Wb + b), then row-normalize.
// 64x64 block tile, 256 threads, 4x4 thread tile, f32x2 accumulators.
// sH/sP padded to stride 17 (16B units) -> conflict-free.
// ---------------------------------------------------------------------------
#define HP_STRIDE 17
__global__ void __launch_bounds__(256, 2) dense_kernel(
        const float4* __restrict__ Wgc, const float* __restrict__ bgc,
        const float4* __restrict__ Wbi, const float* __restrict__ bbi,
        int k) {
    extern __shared__ char smem[];
    ulonglong2* sH  = reinterpret_cast<ulonglong2*>(smem);                 // 64*17*16 = 17408
    ulonglong2* sP  = reinterpret_cast<ulonglong2*>(smem + 17408);         // 17408
    ulonglong2* sWg = reinterpret_cast<ulonglong2*>(smem + 34816);         // 16384
    ulonglong2* sWb = reinterpret_cast<ulonglong2*>(smem + 51200);         // 16384
    float*      sB  = reinterpret_cast<float*>(smem + 67584);              // 256

    const int tid = threadIdx.x;
    const int row0 = blockIdx.x * 64;

    const float4* side4 = reinterpret_cast<const float4*>(g_side);
    const float4* ego4  = reinterpret_cast<const float4*>(g_ego[k]);

    // stage h = side, p = ego*side
    for (int i = tid; i < 64 * 16; i += 256) {
        int r = i >> 4, c = i & 15;
        int rr = row0 + r;
        if (rr >= N_NODES) rr = N_NODES - 1;
        int gidx = rr * 16 + c;
        float4 s = side4[gidx];
        float4 e = ego4[gidx];
        *reinterpret_cast<float4*>(&sH[r * HP_STRIDE + c]) = s;
        *reinterpret_cast<float4*>(&sP[r * HP_STRIDE + c]) =
            make_float4(s.x * e.x, s.y * e.y, s.z * e.z, s.w * e.w);
    }
    // stage W transposed + XOR swizzle: (kk, c) -> sW[c*16 + ((kk>>2) ^ (c&7))].f[kk&3]
    for (int i = tid; i < 64 * 16; i += 256) {
        int kk = i >> 4;
        int c4 = i & 15;
        float4 wg = Wgc[i];
        float4 wb = Wbi[i];
        const float* wgf = reinterpret_cast<const float*>(&wg);
        const float* wbf = reinterpret_cast<const float*>(&wb);
        int k4 = kk >> 2, ksub = kk & 3;
        #pragma unroll
        for (int j = 0; j < 4; j++) {
            int c = c4 * 4 + j;
            int idx = c * 16 + (k4 ^ (c & 7));
            reinterpret_cast<float*>(&sWg[idx])[ksub] = wgf[j];
            reinterpret_cast<float*>(&sWb[idx])[ksub] = wbf[j];
        }
    }
    if (tid < 64) sB[tid] = bgc[tid] + bbi[tid];
    __syncthreads();

    const int cg = tid & 15;
    const int rg = tid >> 4;

    unsigned long long acc[4][4];
    #pragma unroll
    for (int a = 0; a < 4; a++)
        #pragma unroll
        for (int b = 0; b < 4; b++) acc[a][b] = 0ull;

    int ccol[4], widx[4];
    #pragma unroll
    for (int cidx = 0; cidx < 4; cidx++) {
        ccol[cidx] = cidx * 16 + cg;
        widx[cidx] = ccol[cidx] * 16;
    }

    #pragma unroll 4
    for (int k4 = 0; k4 < 16; k4++) {
        ulonglong2 h2[4], p2[4];
        #pragma unroll
        for (int ridx = 0; ridx < 4; ridx++) {
            int r = rg * 4 + ridx;
            h2[ridx] = sH[r * HP_STRIDE + k4];
            p2[ridx] = sP[r * HP_STRIDE + k4];
        }
        ulonglong2 wg2[4], wb2[4];
        #pragma unroll
        for (int cidx = 0; cidx < 4; cidx++) {
            int idx = widx[cidx] + (k4 ^ (ccol[cidx] & 7));
            wg2[cidx] = sWg[idx];
            wb2[cidx] = sWb[idx];
        }
        #pragma unroll
        for (int ridx = 0; ridx < 4; ridx++) {
            #pragma unroll
            for (int cidx = 0; cidx < 4; cidx++) {
                FMA2(acc[ridx][cidx], h2[ridx].x, wg2[cidx].x);
                FMA2(acc[ridx][cidx], h2[ridx].y, wg2[cidx].y);
                FMA2(acc[ridx][cidx], p2[ridx].x, wb2[cidx].x);
                FMA2(acc[ridx][cidx], p2[ridx].y, wb2[cidx].y);
            }
        }
    }

    // epilogue: combine lanes, bias, leaky_relu, row-norm via half-warp shuffle
    float out[4][4];
    float ssr[4];
    #pragma unroll
    for (int ridx = 0; ridx < 4; ridx++) {
        ssr[ridx] = 0.f;
        #pragma unroll
        for (int cidx = 0; cidx < 4; cidx++) {
            float v = f2lo(acc[ridx][cidx]) + f2hi(acc[ridx][cidx]) + sB[ccol[cidx]];
            v = (v > 0.f) ? v : 0.2f * v;
            out[ridx][cidx] = v;
            ssr[ridx] += v * v;
        }
    }
    #pragma unroll
    for (int ridx = 0; ridx < 4; ridx++) {
        float s = ssr[ridx];
        #pragma unroll
        for (int m = 1; m < 16; m <<= 1)
            s += __shfl_xor_sync(0xffffffffu, s, m, 16);
        ssr[ridx] = 1.0f / fmaxf(sqrtf(s), 1e-12f);
    }

    float* __restrict__ egonew  = g_ego[k + 1];
    float* __restrict__ normout = g_norm[k];
    #pragma unroll
    for (int ridx = 0; ridx < 4; ridx++) {
        int row = row0 + rg * 4 + ridx;
        if (row < N_NODES) {
            #pragma unroll
            for (int cidx = 0; cidx < 4; cidx++) {
                float v = out[ridx][cidx];
                egonew [(size_t)row * EMB + ccol[cidx]] = v;
                normout[(size_t)row * EMB + ccol[cidx]] = v * ssr[ridx];
            }
        }
    }
}

// ---------------------------------------------------------------------------
// Final gather: out rows = [ego_init | norm0 | norm1 | norm2] at selected nodes.
// ---------------------------------------------------------------------------
__global__ void gather_kernel(const int* __restrict__ users,
                              const int* __restrict__ pos,
                              const int* __restrict__ neg,
                              float* __restrict__ out) {
    int t = blockIdx.x * blockDim.x + threadIdx.x;
    if (t >= 3 * BATCH * 64) return;
    int q = t & 63;
    int r = t >> 6;
    int s = r / BATCH;
    int b = r - s * BATCH;
    int node = (s == 0) ? users[b] : (N_USER + ((s == 1) ? pos[b] : neg[b]));
    int blk = q >> 4;
    int qq  = q & 15;
    const float* src = (blk == 0) ? g_ego[0] : g_norm[blk - 1];
    float4 v = *reinterpret_cast<const float4*>(src + (size_t)node * EMB + qq * 4);
    reinterpret_cast<float4*>(out)[(size_t)r * 64 + q] = v;
}

// ---------------------------------------------------------------------------
extern "C" void kernel_launch(void* const* d_in, const int* in_sizes, int n_in,
                              void* d_out, int out_size) {
    const int*   users    = (const int*)  d_in[0];
    const int*   pos      = (const int*)  d_in[1];
    const int*   neg      = (const int*)  d_in[2];
    const int*   arow     = (const int*)  d_in[3];
    const int*   acol     = (const int*)  d_in[4];
    const float* aval     = (const float*)d_in[5];
    const float* user_emb = (const float*)d_in[6];
    const float* item_emb = (const float*)d_in[7];
    const float* W_gc     = (const float*)d_in[8];
    const float* b_gc     = (const float*)d_in[9];
    const float* W_bi     = (const float*)d_in[10];
    const float* b_bi     = (const float*)d_in[11];
    float* out = (float*)d_out;

    const int DSMEM = 67584 + 256;
    static int attr_done = 0;
    if (!attr_done) {
        cudaFuncSetAttribute(dense_kernel, cudaFuncAttributeMaxDynamicSharedMemorySize, DSMEM);
        attr_done = 1;
    }

    const int VEC_BLOCKS    = (ROWELEMS / 4 + 255) / 256;       // 9375
    const int EDGE_BLOCKS   = (NNZ + 255) / 256;                // 9375
    const int SPMM_BLOCKS   = (N_NODES * 32 + 255) / 256;       // 18750
    const int DENSE_BLOCKS  = (N_NODES + 63) / 64;              // 2344
    const int GATHER_BLOCKS = (3 * BATCH * 64 + 255) / 256;     // 3072

    // launch order puts layer-0 spmm at index 3 so ncu (-s 5 with the
    // harness's 2 leading launches) profiles it instead of a scan helper.
    init_kernel<<<VEC_BLOCKS, 256>>>((const float4*)user_emb, (const float4*)item_emb);
    csr_prep_kernel<<<CSR_BLOCKS, 256>>>(arow);
    scatter_kernel<<<EDGE_BLOCKS, 256>>>(arow, acol, aval);

    for (int k = 0; k < N_LAYERS; k++) {
        spmm_sorted_kernel<<<SPMM_BLOCKS, 256>>>(k);
        dense_kernel<<<DENSE_BLOCKS, 256, DSMEM>>>(
            (const float4*)(W_gc + k * EMB * EMB), b_gc + k * EMB,
            (const float4*)(W_bi + k * EMB * EMB), b_bi + k * EMB, k);
    }

    gather_kernel<<<GATHER_BLOCKS, 256>>>(users, pos, neg, out);
}

// round 11
// speedup vs baseline: 1.3547x; 1.0553x over previous
#include <cuda_runtime.h>

#define N_USER   50000
#define N_ITEM   100000
#define N_NODES  150000
#define EMB      64
#define N_LAYERS 3
#define NNZ      2400000
#define BATCH    4096
#define ROWELEMS (N_NODES * EMB)     // 9,600,000 floats = 38.4 MB per buffer
#define CSR_BLOCKS 592               // 148 SMs * 4 blocks — fully co-resident
#define NTILES   ((N_NODES + 63) / 64)   // 2344
#define DENSE_GRID 296               // 2 blocks per SM, persistent

// Persistent scratch (static __device__ arrays: no runtime allocation).
__device__ float g_ego[N_LAYERS + 1][ROWELEMS];
__device__ float g_norm[N_LAYERS][ROWELEMS];
__device__ float g_side[ROWELEMS];

// CSR build scratch
__device__ int  g_cnt[N_NODES];
__device__ int  g_off[N_NODES + 1];
__device__ int  g_cur[N_NODES];
__device__ int  g_bsum[CSR_BLOCKS];
__device__ int2 g_edge[NNZ];         // (col, float-bits of val), grouped by row

// grid barrier state (persistent; cnt always returns to 0, gen monotonic)
__device__ unsigned g_bar_cnt = 0;
__device__ unsigned g_bar_gen = 0;

__device__ __forceinline__ void grid_barrier() {
    __syncthreads();
    if (threadIdx.x == 0) {
        unsigned my_gen = atomicAdd(&g_bar_gen, 0u);
        __threadfence();
        if (atomicAdd(&g_bar_cnt, 1u) == CSR_BLOCKS - 1) {
            g_bar_cnt = 0;
            __threadfence();
            atomicAdd(&g_bar_gen, 1u);
        } else {
            while (atomicAdd(&g_bar_gen, 0u) == my_gen) {}
        }
        __threadfence();
    }
    __syncthreads();
}

// packed f32x2 FMA: acc = a*b + acc
#define FMA2(acc, a, b) \
    asm("fma.rn.f32x2 %0, %1, %2, %3;" : "=l"(acc) : "l"(a), "l"(b), "l"(acc))

__device__ __forceinline__ float f2lo(unsigned long long v) {
    return __uint_as_float((unsigned)(v & 0xffffffffull));
}
__device__ __forceinline__ float f2hi(unsigned long long v) {
    return __uint_as_float((unsigned)(v >> 32));
}

// ---------------------------------------------------------------------------
// init: ego0 = concat(user_emb, item_emb)
// ---------------------------------------------------------------------------
__global__ void init_kernel(const float4* __restrict__ ue, const float4* __restrict__ ie) {
    int i = blockIdx.x * blockDim.x + threadIdx.x;
    const int NU4 = N_USER * EMB / 4;
    const int NT4 = ROWELEMS / 4;
    if (i >= NT4) return;
    float4 v = (i < NU4) ? ue[i] : ie[i - NU4];
    reinterpret_cast<float4*>(g_ego[0])[i] = v;
}

// ---------------------------------------------------------------------------
// Fused CSR prep + scatter: zero -> histogram -> scan -> offsets -> scatter.
// Single grid-resident kernel with spin grid barriers (592 blocks, 4/SM).
// ---------------------------------------------------------------------------
__global__ void __launch_bounds__(256) csr_prep_kernel(const int* __restrict__ arow,
                                                       const int* __restrict__ acol,
                                                       const float* __restrict__ aval) {
    const int tid = threadIdx.x;
    const int gid = blockIdx.x * 256 + tid;
    const int nthreads = CSR_BLOCKS * 256;

    // phase 0: zero counts
    for (int i = gid; i < N_NODES; i += nthreads) g_cnt[i] = 0;
    grid_barrier();

    // phase 1: histogram
    for (int e = gid; e < NNZ; e += nthreads) atomicAdd(&g_cnt[arow[e]], 1);
    grid_barrier();

    // phase 2: per-block inclusive scan of 256 counts + block sum
    __shared__ int s[256];
    int myv = (gid < N_NODES) ? g_cnt[gid] : 0;
    s[tid] = myv;
    __syncthreads();
    #pragma unroll
    for (int d = 1; d < 256; d <<= 1) {
        int add = (tid >= d) ? s[tid - d] : 0;
        __syncthreads();
        s[tid] += add;
        __syncthreads();
    }
    int my_incl = s[tid];
    if (tid == 255) g_bsum[blockIdx.x] = s[255];
    grid_barrier();

    // phase 3: block 0 exclusive-scans the block sums (3 chunks of 256, carry)
    if (blockIdx.x == 0) {
        __shared__ int carry;
        if (tid == 0) carry = 0;
        __syncthreads();
        for (int base = 0; base < CSR_BLOCKS; base += 256) {
            int idx = base + tid;
            int v = (idx < CSR_BLOCKS) ? g_bsum[idx] : 0;
            s[tid] = v;
            __syncthreads();
            #pragma unroll
            for (int d = 1; d < 256; d <<= 1) {
                int add = (tid >= d) ? s[tid - d] : 0;
                __syncthreads();
                s[tid] += add;
                __syncthreads();
            }
            if (idx < CSR_BLOCKS) g_bsum[idx] = carry + s[tid] - v;  // exclusive
            __syncthreads();
            if (tid == 0) carry += s[255];
            __syncthreads();
        }
    }
    grid_barrier();

    // phase 4: final offsets
    if (gid < N_NODES) {
        int off = g_bsum[blockIdx.x] + my_incl - myv;
        g_off[gid] = off;
        g_cur[gid] = off;
    }
    if (gid == 0) g_off[N_NODES] = NNZ;
    grid_barrier();

    // phase 5: scatter edges into row-grouped layout
    for (int e = gid; e < NNZ; e += nthreads) {
        int r = arow[e];
        int pos = atomicAdd(&g_cur[r], 1);
        g_edge[pos] = make_int2(acol[e], __float_as_int(aval[e]));
    }
}

// ---------------------------------------------------------------------------
// SpMM over CSR: warp per row, fp32 gather, edge loop unrolled x4.
// At the LTS byte roofline (~680MB/layer through L2) — do not touch.
// ---------------------------------------------------------------------------
__global__ void spmm_sorted_kernel(int ein) {
    int gtid = blockIdx.x * blockDim.x + threadIdx.x;
    int row  = gtid >> 5;
    if (row >= N_NODES) return;
    int lane = threadIdx.x & 31;

    int beg = g_off[row];
    int end = g_off[row + 1];
    const float2* __restrict__ ego2 =
        reinterpret_cast<const float2*>(g_ego[ein]);

    float2 acc = make_float2(0.f, 0.f);
    int e = beg;
    for (; e + 4 <= end; e += 4) {
        int2 c0 = g_edge[e + 0];
        int2 c1 = g_edge[e + 1];
        int2 c2 = g_edge[e + 2];
        int2 c3 = g_edge[e + 3];
        float2 x0 = ego2[c0.x * 32 + lane];
        float2 x1 = ego2[c1.x * 32 + lane];
        float2 x2 = ego2[c2.x * 32 + lane];
        float2 x3 = ego2[c3.x * 32 + lane];
        float v0 = __int_as_float(c0.y);
        float v1 = __int_as_float(c1.y);
        float v2 = __int_as_float(c2.y);
        float v3 = __int_as_float(c3.y);
        acc.x += v0 * x0.x; acc.y += v0 * x0.y;
        acc.x += v1 * x1.x; acc.y += v1 * x1.y;
        acc.x += v2 * x2.x; acc.y += v2 * x2.y;
        acc.x += v3 * x3.x; acc.y += v3 * x3.y;
    }
    for (; e < end; e++) {
        int2 cv = g_edge[e];
        float v = __int_as_float(cv.y);
        float2 x = ego2[cv.x * 32 + lane];
        acc.x += v * x.x;
        acc.y += v * x.y;
    }
    reinterpret_cast<float2*>(g_side + (size_t)row * EMB)[lane] = acc;
}

// ---------------------------------------------------------------------------
// PERSISTENT dense: out = lrelu(h@Wg + (ego*h)@Wb + b), then row-normalize.
// Grid = 296 (2/SM). W staged into smem ONCE per block, then each block
// loops over ~8 tiles of 64 rows. Per tile: stage h/p, FFMA2 mainloop,
// fused epilogue. sH/sP padded to stride 17 (16B units) -> conflict-free.
// ---------------------------------------------------------------------------
#define HP_STRIDE 17
__global__ void __launch_bounds__(256, 2) dense_kernel(
        const float4* __restrict__ Wgc, const float* __restrict__ bgc,
        const float4* __restrict__ Wbi, const float* __restrict__ bbi,
        int k) {
    extern __shared__ char smem[];
    ulonglong2* sH  = reinterpret_cast<ulonglong2*>(smem);                 // 64*17*16 = 17408
    ulonglong2* sP  = reinterpret_cast<ulonglong2*>(smem + 17408);         // 17408
    ulonglong2* sWg = reinterpret_cast<ulonglong2*>(smem + 34816);         // 16384
    ulonglong2* sWb = reinterpret_cast<ulonglong2*>(smem + 51200);         // 16384
    float*      sB  = reinterpret_cast<float*>(smem + 67584);              // 256

    const int tid = threadIdx.x;

    // ---- stage W transposed + XOR swizzle ONCE: (kk,c) -> sW[c*16+((kk>>2)^(c&7))].f[kk&3]
    for (int i = tid; i < 64 * 16; i += 256) {
        int kk = i >> 4;
        int c4 = i & 15;
        float4 wg = Wgc[i];
        float4 wb = Wbi[i];
        const float* wgf = reinterpret_cast<const float*>(&wg);
        const float* wbf = reinterpret_cast<const float*>(&wb);
        int k4 = kk >> 2, ksub = kk & 3;
        #pragma unroll
        for (int j = 0; j < 4; j++) {
            int c = c4 * 4 + j;
            int idx = c * 16 + (k4 ^ (c & 7));
            reinterpret_cast<float*>(&sWg[idx])[ksub] = wgf[j];
            reinterpret_cast<float*>(&sWb[idx])[ksub] = wbf[j];
        }
    }
    if (tid < 64) sB[tid] = bgc[tid] + bbi[tid];
    // (first __syncthreads inside the tile loop covers W visibility)

    const int cg = tid & 15;
    const int rg = tid >> 4;
    int ccol[4], widx[4];
    #pragma unroll
    for (int cidx = 0; cidx < 4; cidx++) {
        ccol[cidx] = cidx * 16 + cg;
        widx[cidx] = ccol[cidx] * 16;
    }

    const float4* side4 = reinterpret_cast<const float4*>(g_side);
    const float4* ego4  = reinterpret_cast<const float4*>(g_ego[k]);
    float* __restrict__ egonew  = g_ego[k + 1];
    float* __restrict__ normout = g_norm[k];

    for (int tile = blockIdx.x; tile < NTILES; tile += DENSE_GRID) {
        const int row0 = tile * 64;

        // ---- stage h = side, p = ego*side for this tile
        for (int i = tid; i < 64 * 16; i += 256) {
            int r = i >> 4, c = i & 15;
            int rr = row0 + r;
            if (rr >= N_NODES) rr = N_NODES - 1;
            int gidx = rr * 16 + c;
            float4 s = side4[gidx];
            float4 e = ego4[gidx];
            *reinterpret_cast<float4*>(&sH[r * HP_STRIDE + c]) = s;
            *reinterpret_cast<float4*>(&sP[r * HP_STRIDE + c]) =
                make_float4(s.x * e.x, s.y * e.y, s.z * e.z, s.w * e.w);
        }
        __syncthreads();

        // ---- FFMA2 mainloop
        unsigned long long acc[4][4];
        #pragma unroll
        for (int a = 0; a < 4; a++)
            #pragma unroll
            for (int b = 0; b < 4; b++) acc[a][b] = 0ull;

        #pragma unroll 4
        for (int k4 = 0; k4 < 16; k4++) {
            ulonglong2 h2[4], p2[4];
            #pragma unroll
            for (int ridx = 0; ridx < 4; ridx++) {
                int r = rg * 4 + ridx;
                h2[ridx] = sH[r * HP_STRIDE + k4];
                p2[ridx] = sP[r * HP_STRIDE + k4];
            }
            ulonglong2 wg2[4], wb2[4];
            #pragma unroll
            for (int cidx = 0; cidx < 4; cidx++) {
                int idx = widx[cidx] + (k4 ^ (ccol[cidx] & 7));
                wg2[cidx] = sWg[idx];
                wb2[cidx] = sWb[idx];
            }
            #pragma unroll
            for (int ridx = 0; ridx < 4; ridx++) {
                #pragma unroll
                for (int cidx = 0; cidx < 4; cidx++) {
                    FMA2(acc[ridx][cidx], h2[ridx].x, wg2[cidx].x);
                    FMA2(acc[ridx][cidx], h2[ridx].y, wg2[cidx].y);
                    FMA2(acc[ridx][cidx], p2[ridx].x, wb2[cidx].x);
                    FMA2(acc[ridx][cidx], p2[ridx].y, wb2[cidx].y);
                }
            }
        }

        // ---- epilogue: lanes, bias, leaky_relu, row-norm via half-warp shuffle
        float out[4][4];
        float ssr[4];
        #pragma unroll
        for (int ridx = 0; ridx < 4; ridx++) {
            ssr[ridx] = 0.f;
            #pragma unroll
            for (int cidx = 0; cidx < 4; cidx++) {
                float v = f2lo(acc[ridx][cidx]) + f2hi(acc[ridx][cidx]) + sB[ccol[cidx]];
                v = (v > 0.f) ? v : 0.2f * v;
                out[ridx][cidx] = v;
                ssr[ridx] += v * v;
            }
        }
        #pragma unroll
        for (int ridx = 0; ridx < 4; ridx++) {
            float s = ssr[ridx];
            #pragma unroll
            for (int m = 1; m < 16; m <<= 1)
                s += __shfl_xor_sync(0xffffffffu, s, m, 16);
            ssr[ridx] = 1.0f / fmaxf(sqrtf(s), 1e-12f);
        }

        #pragma unroll
        for (int ridx = 0; ridx < 4; ridx++) {
            int row = row0 + rg * 4 + ridx;
            if (row < N_NODES) {
                #pragma unroll
                for (int cidx = 0; cidx < 4; cidx++) {
                    float v = out[ridx][cidx];
                    egonew [(size_t)row * EMB + ccol[cidx]] = v;
                    normout[(size_t)row * EMB + ccol[cidx]] = v * ssr[ridx];
                }
            }
        }
        __syncthreads();   // protect sH/sP from next tile's staging
    }
}

// ---------------------------------------------------------------------------
// Final gather: out rows = [ego_init | norm0 | norm1 | norm2] at selected nodes.
// ---------------------------------------------------------------------------
__global__ void gather_kernel(const int* __restrict__ users,
                              const int* __restrict__ pos,
                              const int* __restrict__ neg,
                              float* __restrict__ out) {
    int t = blockIdx.x * blockDim.x + threadIdx.x;
    if (t >= 3 * BATCH * 64) return;
    int q = t & 63;
    int r = t >> 6;
    int s = r / BATCH;
    int b = r - s * BATCH;
    int node = (s == 0) ? users[b] : (N_USER + ((s == 1) ? pos[b] : neg[b]));
    int blk = q >> 4;
    int qq  = q & 15;
    const float* src = (blk == 0) ? g_ego[0] : g_norm[blk - 1];
    float4 v = *reinterpret_cast<const float4*>(src + (size_t)node * EMB + qq * 4);
    reinterpret_cast<float4*>(out)[(size_t)r * 64 + q] = v;
}

// ---------------------------------------------------------------------------
extern "C" void kernel_launch(void* const* d_in, const int* in_sizes, int n_in,
                              void* d_out, int out_size) {
    const int*   users    = (const int*)  d_in[0];
    const int*   pos      = (const int*)  d_in[1];
    const int*   neg      = (const int*)  d_in[2];
    const int*   arow     = (const int*)  d_in[3];
    const int*   acol     = (const int*)  d_in[4];
    const float* aval     = (const float*)d_in[5];
    const float* user_emb = (const float*)d_in[6];
    const float* item_emb = (const float*)d_in[7];
    const float* W_gc     = (const float*)d_in[8];
    const float* b_gc     = (const float*)d_in[9];
    const float* W_bi     = (const float*)d_in[10];
    const float* b_bi     = (const float*)d_in[11];
    float* out = (float*)d_out;

    const int DSMEM = 67584 + 256;
    static int attr_done = 0;
    if (!attr_done) {
        cudaFuncSetAttribute(dense_kernel, cudaFuncAttributeMaxDynamicSharedMemorySize, DSMEM);
        attr_done = 1;
    }

    const int VEC_BLOCKS    = (ROWELEMS / 4 + 255) / 256;       // 9375
    const int SPMM_BLOCKS   = (N_NODES * 32 + 255) / 256;       // 18750
    const int GATHER_BLOCKS = (3 * BATCH * 64 + 255) / 256;     // 3072

    // launch order puts layer-0 DENSE at index 4 so ncu profiles it this time.
    init_kernel<<<VEC_BLOCKS, 256>>>((const float4*)user_emb, (const float4*)item_emb);
    csr_prep_kernel<<<CSR_BLOCKS, 256>>>(arow, acol, aval);

    for (int k = 0; k < N_LAYERS; k++) {
        spmm_sorted_kernel<<<SPMM_BLOCKS, 256>>>(k);
        dense_kernel<<<DENSE_GRID, 256, DSMEM>>>(
            (const float4*)(W_gc + k * EMB * EMB), b_gc + k * EMB,
            (const float4*)(W_bi + k * EMB * EMB), b_bi + k * EMB, k);
    }

    gather_kernel<<<GATHER_BLOCKS, 256>>>(users, pos, neg, out);
}

// round 12
// speedup vs baseline: 1.4299x; 1.0555x over previous
#include <cuda_runtime.h>
#include <cuda_fp16.h>
#include <cstdint>

#define N_USER   50000
#define N_ITEM   100000
#define N_NODES  150000
#define EMB      64
#define N_LAYERS 3
#define NNZ      2400000
#define BATCH    4096
#define ROWELEMS (N_NODES * EMB)     // 9,600,000 floats = 38.4 MB per buffer
#define CSR_BLOCKS 592               // 148 SMs * 4 blocks — fully co-resident
#define NTILES   ((N_NODES + 63) / 64)   // 2344
#define DENSE_GRID 296               // 2 blocks per SM, persistent

// Persistent scratch (static __device__ arrays: no runtime allocation).
__device__ float  g_ego[N_LAYERS + 1][ROWELEMS];
__device__ float  g_norm[N_LAYERS][ROWELEMS];
__device__ float  g_side[ROWELEMS];
__device__ __half g_egoh[ROWELEMS];  // fp16 mirror of CURRENT layer ego (spmm gather operand)

// CSR build scratch
__device__ int  g_cnt[N_NODES];
__device__ int  g_off[N_NODES + 1];
__device__ int  g_cur[N_NODES];
__device__ int  g_bsum[CSR_BLOCKS];
__device__ int2 g_edge[NNZ];         // (col, float-bits of val), grouped by row

// grid barrier state (persistent; cnt always returns to 0, gen monotonic)
__device__ unsigned g_bar_cnt = 0;
__device__ unsigned g_bar_gen = 0;

__device__ __forceinline__ void grid_barrier() {
    __syncthreads();
    if (threadIdx.x == 0) {
        unsigned my_gen = atomicAdd(&g_bar_gen, 0u);
        __threadfence();
        if (atomicAdd(&g_bar_cnt, 1u) == CSR_BLOCKS - 1) {
            g_bar_cnt = 0;
            __threadfence();
            atomicAdd(&g_bar_gen, 1u);
        } else {
            while (atomicAdd(&g_bar_gen, 0u) == my_gen) {}
        }
        __threadfence();
    }
    __syncthreads();
}

// packed f32x2 ops
#define FMA2(acc, a, b) \
    asm("fma.rn.f32x2 %0, %1, %2, %3;" : "=l"(acc) : "l"(a), "l"(b), "l"(acc))
#define MUL2(d, a, b) \
    asm("mul.rn.f32x2 %0, %1, %2;" : "=l"(d) : "l"(a), "l"(b))

__device__ __forceinline__ float f2lo(unsigned long long v) {
    return __uint_as_float((unsigned)(v & 0xffffffffull));
}
__device__ __forceinline__ float f2hi(unsigned long long v) {
    return __uint_as_float((unsigned)(v >> 32));
}

__device__ __forceinline__ void cp_async16(uint32_t dst, const void* src) {
    asm volatile("cp.async.cg.shared.global [%0], [%1], 16;" :: "r"(dst), "l"(src));
}

// ---------------------------------------------------------------------------
// init: ego0 = concat(user_emb, item_emb) + fp16 mirror
// ---------------------------------------------------------------------------
__global__ void init_kernel(const float4* __restrict__ ue, const float4* __restrict__ ie) {
    int i = blockIdx.x * blockDim.x + threadIdx.x;
    const int NU4 = N_USER * EMB / 4;
    const int NT4 = ROWELEMS / 4;
    if (i >= NT4) return;
    float4 v = (i < NU4) ? ue[i] : ie[i - NU4];
    reinterpret_cast<float4*>(g_ego[0])[i] = v;
    __half2* h2 = reinterpret_cast<__half2*>(g_egoh) + i * 2;
    h2[0] = __floats2half2_rn(v.x, v.y);
    h2[1] = __floats2half2_rn(v.z, v.w);
}

// ---------------------------------------------------------------------------
// Fused CSR prep + scatter (grid-resident, spin grid barriers)
// ---------------------------------------------------------------------------
__global__ void __launch_bounds__(256) csr_prep_kernel(const int* __restrict__ arow,
                                                       const int* __restrict__ acol,
                                                       const float* __restrict__ aval) {
    const int tid = threadIdx.x;
    const int gid = blockIdx.x * 256 + tid;
    const int nthreads = CSR_BLOCKS * 256;

    for (int i = gid; i < N_NODES; i += nthreads) g_cnt[i] = 0;
    grid_barrier();

    for (int e = gid; e < NNZ; e += nthreads) atomicAdd(&g_cnt[arow[e]], 1);
    grid_barrier();

    __shared__ int s[256];
    int myv = (gid < N_NODES) ? g_cnt[gid] : 0;
    s[tid] = myv;
    __syncthreads();
    #pragma unroll
    for (int d = 1; d < 256; d <<= 1) {
        int add = (tid >= d) ? s[tid - d] : 0;
        __syncthreads();
        s[tid] += add;
        __syncthreads();
    }
    int my_incl = s[tid];
    if (tid == 255) g_bsum[blockIdx.x] = s[255];
    grid_barrier();

    if (blockIdx.x == 0) {
        __shared__ int carry;
        if (tid == 0) carry = 0;
        __syncthreads();
        for (int base = 0; base < CSR_BLOCKS; base += 256) {
            int idx = base + tid;
            int v = (idx < CSR_BLOCKS) ? g_bsum[idx] : 0;
            s[tid] = v;
            __syncthreads();
            #pragma unroll
            for (int d = 1; d < 256; d <<= 1) {
                int add = (tid >= d) ? s[tid - d] : 0;
                __syncthreads();
                s[tid] += add;
                __syncthreads();
            }
            if (idx < CSR_BLOCKS) g_bsum[idx] = carry + s[tid] - v;  // exclusive
            __syncthreads();
            if (tid == 0) carry += s[255];
            __syncthreads();
        }
    }
    grid_barrier();

    if (gid < N_NODES) {
        int off = g_bsum[blockIdx.x] + my_incl - myv;
        g_off[gid] = off;
        g_cur[gid] = off;
    }
    if (gid == 0) g_off[N_NODES] = NNZ;
    grid_barrier();

    for (int e = gid; e < NNZ; e += nthreads) {
        int r = arow[e];
        int pos = atomicAdd(&g_cur[r], 1);
        g_edge[pos] = make_int2(acol[e], __float_as_int(aval[e]));
    }
}

// ---------------------------------------------------------------------------
// SpMM over CSR: warp per row, fp16 gather (halves L2 bytes: ~340MB/layer),
// fp32 accumulate, edge loop x4 unrolled, one 256B fp32 store per row.
// ---------------------------------------------------------------------------
__global__ void spmm_sorted_kernel() {
    int gtid = blockIdx.x * blockDim.x + threadIdx.x;
    int row  = gtid >> 5;
    if (row >= N_NODES) return;
    int lane = threadIdx.x & 31;

    int beg = g_off[row];
    int end = g_off[row + 1];
    const __half2* __restrict__ egoh = reinterpret_cast<const __half2*>(g_egoh);

    float2 acc = make_float2(0.f, 0.f);
    int e = beg;
    for (; e + 4 <= end; e += 4) {
        int2 c0 = g_edge[e + 0];
        int2 c1 = g_edge[e + 1];
        int2 c2 = g_edge[e + 2];
        int2 c3 = g_edge[e + 3];
        __half2 x0 = egoh[c0.x * 32 + lane];
        __half2 x1 = egoh[c1.x * 32 + lane];
        __half2 x2 = egoh[c2.x * 32 + lane];
        __half2 x3 = egoh[c3.x * 32 + lane];
        float2 f0 = __half22float2(x0);
        float2 f1 = __half22float2(x1);
        float2 f2 = __half22float2(x2);
        float2 f3 = __half22float2(x3);
        float v0 = __int_as_float(c0.y);
        float v1 = __int_as_float(c1.y);
        float v2 = __int_as_float(c2.y);
        float v3 = __int_as_float(c3.y);
        acc.x += v0 * f0.x; acc.y += v0 * f0.y;
        acc.x += v1 * f1.x; acc.y += v1 * f1.y;
        acc.x += v2 * f2.x; acc.y += v2 * f2.y;
        acc.x += v3 * f3.x; acc.y += v3 * f3.y;
    }
    for (; e < end; e++) {
        int2 cv = g_edge[e];
        float v = __int_as_float(cv.y);
        float2 f = __half22float2(egoh[cv.x * 32 + lane]);
        acc.x += v * f.x;
        acc.y += v * f.y;
    }
    reinterpret_cast<float2*>(g_side + (size_t)row * EMB)[lane] = acc;
}

// ---------------------------------------------------------------------------
// PERSISTENT + PIPELINED dense. Grid = 296 (2/SM). W staged once per block.
// Tile loop double-buffers side/ego via cp.async: stage t+1 while computing t.
// p = h*e computed in mainloop (MUL2). Column map: thread owns 4 CONSECUTIVE
// cols (ccol = cg*4 + cidx) -> float4 epilogue stores + coalesced fp16 mirror.
// W swizzle keyed on cg (c>>2)&7: 16 distinct 16B units over 8 bank-quads.
// ---------------------------------------------------------------------------
#define HP_STRIDE 17
#define SM_H(b)  ((b) * 17408)
#define SM_E(b)  (34816 + (b) * 17408)
#define SM_WG    69632
#define SM_WB    86016
#define SM_B     102400
#define DSMEM_SZ 102656

__global__ void __launch_bounds__(256, 2) dense_kernel(
        const float4* __restrict__ Wgc, const float* __restrict__ bgc,
        const float4* __restrict__ Wbi, const float* __restrict__ bbi,
        int k) {
    extern __shared__ char smem[];
    uint32_t smem_u32 = (uint32_t)__cvta_generic_to_shared(smem);
    float* sB = reinterpret_cast<float*>(smem + SM_B);

    const int tid = threadIdx.x;
    const float4* side4 = reinterpret_cast<const float4*>(g_side);
    const float4* ego4  = reinterpret_cast<const float4*>(g_ego[k]);

    // ---- stage W ONCE: (kk,c) -> unit c*16 + (k4 ^ ((c>>2)&7)), float ksub
    for (int i = tid; i < 64 * 16; i += 256) {
        int kk = i >> 4;
        int c4 = i & 15;
        float4 wg = Wgc[i];
        float4 wb = Wbi[i];
        const float* wgf = reinterpret_cast<const float*>(&wg);
        const float* wbf = reinterpret_cast<const float*>(&wb);
        int k4 = kk >> 2, ksub = kk & 3;
        #pragma unroll
        for (int j = 0; j < 4; j++) {
            int c = c4 * 4 + j;
            int idx = (c * 16 + (k4 ^ ((c >> 2) & 7))) * 4 + ksub;   // float index
            reinterpret_cast<float*>(smem + SM_WG)[idx] = wgf[j];
            reinterpret_cast<float*>(smem + SM_WB)[idx] = wbf[j];
        }
    }
    if (tid < 64) sB[tid] = bgc[tid] + bbi[tid];

    // staging lambda-equivalent: 4 float4 of side + 4 of ego per thread per tile
    const int sr = tid >> 6;             // base row group for staging (0..3)
    const int sc = tid & 63;             // (row offset within group, col) packed
    // iterate i = tid + j*256: r = i>>4, c = i&15
    auto stage_tile = [&](int tile, int buf) {
        #pragma unroll
        for (int j = 0; j < 4; j++) {
            int i = tid + j * 256;
            int r = i >> 4, c = i & 15;
            int rr = tile * 64 + r;
            if (rr >= N_NODES) rr = N_NODES - 1;
            const float4* srcS = side4 + rr * 16 + c;
            const float4* srcE = ego4  + rr * 16 + c;
            uint32_t off = (uint32_t)(r * HP_STRIDE + c) * 16;
            cp_async16(smem_u32 + SM_H(buf) + off, srcS);
            cp_async16(smem_u32 + SM_E(buf) + off, srcE);
        }
    };

    const int cg = tid & 15;
    const int rg = tid >> 4;
    int ccol0 = cg * 4;                  // 4 consecutive output cols
    int widx[4];
    #pragma unroll
    for (int cidx = 0; cidx < 4; cidx++) widx[cidx] = (ccol0 + cidx) * 16;
    const int swkey = cg & 7;

    float* __restrict__ egonew  = g_ego[k + 1];
    float* __restrict__ normout = g_norm[k];
    __half* __restrict__ egoh   = g_egoh;
    const bool write_mirror = (k + 1 < N_LAYERS);

    int tile = blockIdx.x;
    int buf = 0;
    stage_tile(tile, 0);
    asm volatile("cp.async.commit_group;");
    asm volatile("cp.async.wait_group 0;");
    __syncthreads();

    const ulonglong2* sWg = reinterpret_cast<const ulonglong2*>(smem + SM_WG);
    const ulonglong2* sWb = reinterpret_cast<const ulonglong2*>(smem + SM_WB);

    while (tile < NTILES) {
        int next = tile + DENSE_GRID;
        if (next < NTILES) stage_tile(next, buf ^ 1);
        asm volatile("cp.async.commit_group;");

        const ulonglong2* sH = reinterpret_cast<const ulonglong2*>(smem + SM_H(buf));
        const ulonglong2* sE = reinterpret_cast<const ulonglong2*>(smem + SM_E(buf));

        unsigned long long acc[4][4];
        #pragma unroll
        for (int a = 0; a < 4; a++)
            #pragma unroll
            for (int b = 0; b < 4; b++) acc[a][b] = 0ull;

        #pragma unroll 4
        for (int k4 = 0; k4 < 16; k4++) {
            ulonglong2 h2[4], p2[4];
            #pragma unroll
            for (int ridx = 0; ridx < 4; ridx++) {
                int r = rg * 4 + ridx;
                h2[ridx] = sH[r * HP_STRIDE + k4];
                ulonglong2 e2 = sE[r * HP_STRIDE + k4];
                MUL2(p2[ridx].x, h2[ridx].x, e2.x);
                MUL2(p2[ridx].y, h2[ridx].y, e2.y);
            }
            int swz = k4 ^ swkey;
            ulonglong2 wg2[4], wb2[4];
            #pragma unroll
            for (int cidx = 0; cidx < 4; cidx++) {
                wg2[cidx] = sWg[widx[cidx] + swz];
                wb2[cidx] = sWb[widx[cidx] + swz];
            }
            #pragma unroll
            for (int ridx = 0; ridx < 4; ridx++) {
                #pragma unroll
                for (int cidx = 0; cidx < 4; cidx++) {
                    FMA2(acc[ridx][cidx], h2[ridx].x, wg2[cidx].x);
                    FMA2(acc[ridx][cidx], h2[ridx].y, wg2[cidx].y);
                    FMA2(acc[ridx][cidx], p2[ridx].x, wb2[cidx].x);
                    FMA2(acc[ridx][cidx], p2[ridx].y, wb2[cidx].y);
                }
            }
        }

        // epilogue: lanes, bias, lrelu, row-norm (16-lane shuffle), stores
        float out[4][4];
        float ssr[4];
        #pragma unroll
        for (int ridx = 0; ridx < 4; ridx++) {
            ssr[ridx] = 0.f;
            #pragma unroll
            for (int cidx = 0; cidx < 4; cidx++) {
                float v = f2lo(acc[ridx][cidx]) + f2hi(acc[ridx][cidx]) + sB[ccol0 + cidx];
                v = (v > 0.f) ? v : 0.2f * v;
                out[ridx][cidx] = v;
                ssr[ridx] += v * v;
            }
        }
        #pragma unroll
        for (int ridx = 0; ridx < 4; ridx++) {
            float s = ssr[ridx];
            #pragma unroll
            for (int m = 1; m < 16; m <<= 1)
                s += __shfl_xor_sync(0xffffffffu, s, m, 16);
            ssr[ridx] = 1.0f / fmaxf(sqrtf(s), 1e-12f);
        }

        #pragma unroll
        for (int ridx = 0; ridx < 4; ridx++) {
            int row = tile * 64 + rg * 4 + ridx;
            if (row < N_NODES) {
                float4 v = make_float4(out[ridx][0], out[ridx][1],
                                       out[ridx][2], out[ridx][3]);
                float inv = ssr[ridx];
                reinterpret_cast<float4*>(egonew + (size_t)row * EMB)[cg] = v;
                reinterpret_cast<float4*>(normout + (size_t)row * EMB)[cg] =
                    make_float4(v.x * inv, v.y * inv, v.z * inv, v.w * inv);
                if (write_mirror) {
                    __half2 m0 = __floats2half2_rn(v.x, v.y);
                    __half2 m1 = __floats2half2_rn(v.z, v.w);
                    uint2 mm = make_uint2(*reinterpret_cast<uint32_t*>(&m0),
                                          *reinterpret_cast<uint32_t*>(&m1));
                    *reinterpret_cast<uint2*>(egoh + (size_t)row * EMB + ccol0) = mm;
                }
            }
        }

        asm volatile("cp.async.wait_group 0;");
        __syncthreads();
        tile = next;
        buf ^= 1;
    }
}

// ---------------------------------------------------------------------------
// Final gather: out rows = [ego_init | norm0 | norm1 | norm2] at selected nodes.
// ---------------------------------------------------------------------------
__global__ void gather_kernel(const int* __restrict__ users,
                              const int* __restrict__ pos,
                              const int* __restrict__ neg,
                              float* __restrict__ out) {
    int t = blockIdx.x * blockDim.x + threadIdx.x;
    if (t >= 3 * BATCH * 64) return;
    int q = t & 63;
    int r = t >> 6;
    int s = r / BATCH;
    int b = r - s * BATCH;
    int node = (s == 0) ? users[b] : (N_USER + ((s == 1) ? pos[b] : neg[b]));
    int blk = q >> 4;
    int qq  = q & 15;
    const float* src = (blk == 0) ? g_ego[0] : g_norm[blk - 1];
    float4 v = *reinterpret_cast<const float4*>(src + (size_t)node * EMB + qq * 4);
    reinterpret_cast<float4*>(out)[(size_t)r * 64 + q] = v;
}

// ---------------------------------------------------------------------------
extern "C" void kernel_launch(void* const* d_in, const int* in_sizes, int n_in,
                              void* d_out, int out_size) {
    const int*   users    = (const int*)  d_in[0];
    const int*   pos      = (const int*)  d_in[1];
    const int*   neg      = (const int*)  d_in[2];
    const int*   arow     = (const int*)  d_in[3];
    const int*   acol     = (const int*)  d_in[4];
    const float* aval     = (const float*)d_in[5];
    const float* user_emb = (const float*)d_in[6];
    const float* item_emb = (const float*)d_in[7];
    const float* W_gc     = (const float*)d_in[8];
    const float* b_gc     = (const float*)d_in[9];
    const float* W_bi     = (const float*)d_in[10];
    const float* b_bi     = (const float*)d_in[11];
    float* out = (float*)d_out;

    static int attr_done = 0;
    if (!attr_done) {
        cudaFuncSetAttribute(dense_kernel, cudaFuncAttributeMaxDynamicSharedMemorySize, DSMEM_SZ);
        attr_done = 1;
    }

    const int VEC_BLOCKS    = (ROWELEMS / 4 + 255) / 256;       // 9375
    const int SPMM_BLOCKS   = (N_NODES * 32 + 255) / 256;       // 18750
    const int GATHER_BLOCKS = (3 * BATCH * 64 + 255) / 256;     // 3072

    init_kernel<<<VEC_BLOCKS, 256>>>((const float4*)user_emb, (const float4*)item_emb);
    csr_prep_kernel<<<CSR_BLOCKS, 256>>>(arow, acol, aval);

    for (int k = 0; k < N_LAYERS; k++) {
        spmm_sorted_kernel<<<SPMM_BLOCKS, 256>>>();
        dense_kernel<<<DENSE_GRID, 256, DSMEM_SZ>>>(
            (const float4*)(W_gc + k * EMB * EMB), b_gc + k * EMB,
            (const float4*)(W_bi + k * EMB * EMB), b_bi + k * EMB, k);
    }

    gather_kernel<<<GATHER_BLOCKS, 256>>>(users, pos, neg, out);
}